// round 8
// baseline (speedup 1.0000x reference)
#include <cuda_runtime.h>
#include <cstdint>

// Model_35347580846430: reflect-pad depthwise moving average, W=25, PAD=12
// x: [B=64, T=4096, N=128] f32, out same shape.
// out[b,t,n] = mean_{k=-12..12} x[b, reflect(t+k), n]
//
// R8: R7's cp.async tile scheme + DOUBLE BUFFERING across a 4-tile strip per
// block. R7 serialized load->wait->compute per block (DRAM 63.9% busy, bubbles
// whenever resident blocks aligned in compute phase). Now each block issues
// tile i+1's 76KB of cp.asyncs BEFORE waiting on tile i (wait_group 1), so
// loads are in flight during every compute phase. Halo re-reads dedup in L2
// (R7 measured 216MB DRAM traffic, below the naive floor).

#define B_DIM   64
#define T_DIM   4096
#define N_DIM   128
#define PAD     12
#define WIN     25
#define T_TILE  128
#define HALO    (2 * PAD)            // 24
#define ROWS    (T_TILE + HALO)      // 152 smem rows per buffer
#define N4      (N_DIM / 4)          // 32 float4 per row
#define NTHR    256
#define K_TILES 4
#define T_STRIP (T_TILE * K_TILES)   // 512
#define SMEM_BYTES (2 * ROWS * N_DIM * 4)   // 155648 (152 KB)

__device__ __forceinline__ int reflect_idx(int t) {
    // np.pad 'reflect': x[-1] -> x[1], x[T] -> x[T-2]
    t = (t < 0) ? -t : t;
    t = (t >= T_DIM) ? (2 * (T_DIM - 1) - t) : t;
    return t;
}

__global__ __launch_bounds__(NTHR)
void ma25_kernel(const float4* __restrict__ x, float4* __restrict__ out) {
    extern __shared__ float4 smem[];          // [2][ROWS][N4]

    const int tid  = threadIdx.x;
    const int lane = tid & 31;                // float4 column 0..31
    const int grp  = tid >> 5;                // 0..7
    const int b    = blockIdx.y;
    const int s0   = blockIdx.x * T_STRIP;    // strip start (t)

    const float4* __restrict__ xb = x + (size_t)b * T_DIM * N4 + lane;
    const float inv = 1.0f / (float)WIN;

    // ---- async tile loader: 152 rows, 8 rows/iter, 19 cp.asyncs per thread
    auto load_tile = [&](int tile, int buf) {
        const int t0 = s0 + tile * T_TILE;
        float4* dstb = smem + buf * (ROWS * N4);
        #pragma unroll
        for (int it = 0; it < ROWS / 8; it++) {
            const int r = it * 8 + grp;
            const int t = reflect_idx(t0 - PAD + r);
            const float4* src = xb + (size_t)t * N4;
            uint32_t dst = (uint32_t)__cvta_generic_to_shared(&dstb[r * N4 + lane]);
            asm volatile("cp.async.cg.shared.global [%0], [%1], 16;"
                         :: "r"(dst), "l"(src) : "memory");
        }
        asm volatile("cp.async.commit_group;" ::: "memory");
    };

    load_tile(0, 0);

    #pragma unroll
    for (int i = 0; i < K_TILES; i++) {
        // Prefetch next tile before consuming current one.
        if (i + 1 < K_TILES) {
            load_tile(i + 1, (i + 1) & 1);
            asm volatile("cp.async.wait_group 1;" ::: "memory");
        } else {
            asm volatile("cp.async.wait_group 0;" ::: "memory");
        }
        __syncthreads();

        // ---- compute tile i from buffer i&1 (R7 scheme)
        const float4* bs = smem + (i & 1) * (ROWS * N4);
        const int r0 = grp * 16;
        float4* __restrict__ ob =
            out + (size_t)(b * T_DIM + s0 + i * T_TILE) * N4 + lane;

        float sx = 0.f, sy = 0.f, sz = 0.f, sw = 0.f;
        #pragma unroll
        for (int j = 0; j < HALO; j++) {
            float4 v = bs[(r0 + j) * N4 + lane];
            sx += v.x; sy += v.y; sz += v.z; sw += v.w;
        }

        #pragma unroll
        for (int k = 0; k < 16; k++) {
            const int r = r0 + k;
            float4 vin = bs[(r + HALO) * N4 + lane];
            float wx = sx + vin.x, wy = sy + vin.y, wz = sz + vin.z, ww = sw + vin.w;

            float4 o; o.x = wx * inv; o.y = wy * inv; o.z = wz * inv; o.w = ww * inv;
            ob[(size_t)r * N4] = o;

            float4 vout = bs[r * N4 + lane];
            sx = wx - vout.x; sy = wy - vout.y; sz = wz - vout.z; sw = ww - vout.w;
        }

        // Buffer i&1 gets overwritten by load_tile(i+2) next iteration:
        // all threads must finish reading it first.
        __syncthreads();
    }
}

extern "C" void kernel_launch(void* const* d_in, const int* in_sizes, int n_in,
                              void* d_out, int out_size) {
    const float4* x = (const float4*)d_in[0];
    float4* out = (float4*)d_out;

    cudaFuncSetAttribute(ma25_kernel,
                         cudaFuncAttributeMaxDynamicSharedMemorySize, SMEM_BYTES);

    dim3 block(NTHR);
    dim3 grid(T_DIM / T_STRIP, B_DIM);             // (8, 64) = 512 blocks
    ma25_kernel<<<grid, block, SMEM_BYTES>>>(x, out);
}